// round 10
// baseline (speedup 1.0000x reference)
#include <cuda_runtime.h>
#include <cstddef>

#define NTOK 2304   // 48*48
#define CCH  256
#define BB   2
#define HS   48

// ---------------- scratch (no allocations allowed) ----------------
__device__ float g_qkv[(size_t)BB * 768 * NTOK];  // rows 0..511 = qk, 512..767 = v
__device__ float g_o  [(size_t)BB * CCH * NTOK];  // attention out
__device__ float g_pe [(size_t)BB * CCH * NTOK];  // depthwise-conv positional term
__device__ float g_x1 [(size_t)BB * CCH * NTOK];
__device__ float g_h  [(size_t)BB * 512 * NTOK];

// ---------------- packed f32x2 helpers (SASS FFMA2 — only reachable via PTX) ----
__device__ __forceinline__ unsigned long long pk2(float lo, float hi) {
    unsigned long long r;
    asm("mov.b64 %0, {%1, %2};" : "=l"(r) : "f"(lo), "f"(hi));
    return r;
}
__device__ __forceinline__ void upk2(unsigned long long v, float& lo, float& hi) {
    asm("mov.b64 {%0, %1}, %2;" : "=f"(lo), "=f"(hi) : "l"(v));
}
__device__ __forceinline__ unsigned long long fma2(unsigned long long a,
                                                   unsigned long long b,
                                                   unsigned long long c) {
    unsigned long long d;
    asm("fma.rn.f32x2 %0, %1, %2, %3;" : "=l"(d) : "l"(a), "l"(b), "l"(c));
    return d;
}

// ---------------- cp.async helpers ----------------
__device__ __forceinline__ void cpasync16(const void* smem, const void* gmem) {
    unsigned sa = (unsigned)__cvta_generic_to_shared(smem);
    asm volatile("cp.async.cg.shared.global [%0], [%1], 16;" :: "r"(sa), "l"(gmem));
}
__device__ __forceinline__ void cpasync_commit() {
    asm volatile("cp.async.commit_group;");
}

// ================= double-buffered cp.async GEMM ==========================
// out[b][m][n] = sum_k W[m][k] * X[b][k][n] + bias[m]
// EPI: 0 none, 1 silu, 2 residual-add(res). Blocks with m0>=msplit use W2/b2.
template<int EPI>
__global__ void __launch_bounds__(256)
gemm_db(int Cin,
        const float* __restrict__ W, const float* __restrict__ bias,
        const float* __restrict__ W2, const float* __restrict__ b2, int msplit,
        const float* __restrict__ X, int xBS,
        float* __restrict__ out, int outBS,
        const float* __restrict__ res)
{
    const int b  = blockIdx.z;
    const int n0 = blockIdx.x * 64;
    const int m0 = blockIdx.y * 64;
    const float* Xb = X + (size_t)b * xBS;

    const float* Wu = W;
    const float* bu = bias;
    int mrow = m0;
    if (m0 >= msplit) { Wu = W2; bu = b2; mrow = m0 - msplit; }

    __shared__ __align__(16) float ws[2][64][20];  // [m][k], row padded to 80B
    __shared__ __align__(16) float xs[2][16][68];  // [k][n], row padded to 272B

    const int tx = threadIdx.x & 15;
    const int ty = threadIdx.x >> 4;
    // cp.async task mapping (one 16B chunk per array per thread)
    const int wrow = threadIdx.x >> 2;          // 0..63
    const int wkc  = (threadIdx.x & 3) * 4;     // 0,4,8,12
    const int xrow = threadIdx.x >> 4;          // 0..15
    const int xcc  = (threadIdx.x & 15) * 4;    // 0..60

    unsigned long long acc2[4][2] = {};

    // prologue: stage tile 0
    cpasync16(&ws[0][wrow][wkc], &Wu[(size_t)(mrow + wrow) * Cin + wkc]);
    cpasync16(&xs[0][xrow][xcc], &Xb[(size_t)xrow * NTOK + n0 + xcc]);
    cpasync_commit();

    const int steps = Cin >> 4;
    for (int t = 0; t < steps; t++) {
        const int cur = t & 1;
        if (t + 1 < steps) {
            const int k0 = (t + 1) << 4;
            cpasync16(&ws[cur ^ 1][wrow][wkc], &Wu[(size_t)(mrow + wrow) * Cin + k0 + wkc]);
            cpasync16(&xs[cur ^ 1][xrow][xcc], &Xb[(size_t)(k0 + xrow) * NTOK + n0 + xcc]);
            cpasync_commit();
            asm volatile("cp.async.wait_group 1;");
        } else {
            asm volatile("cp.async.wait_group 0;");
        }
        __syncthreads();
#pragma unroll
        for (int k = 0; k < 16; k++) {
            ulonglong2 bp = *(const ulonglong2*)&xs[cur][k][tx * 4];
            float a0 = ws[cur][ty * 4 + 0][k];
            float a1 = ws[cur][ty * 4 + 1][k];
            float a2 = ws[cur][ty * 4 + 2][k];
            float a3 = ws[cur][ty * 4 + 3][k];
            unsigned long long ax = pk2(a0, a0), ay = pk2(a1, a1);
            unsigned long long az = pk2(a2, a2), aw = pk2(a3, a3);
            acc2[0][0] = fma2(ax, bp.x, acc2[0][0]); acc2[0][1] = fma2(ax, bp.y, acc2[0][1]);
            acc2[1][0] = fma2(ay, bp.x, acc2[1][0]); acc2[1][1] = fma2(ay, bp.y, acc2[1][1]);
            acc2[2][0] = fma2(az, bp.x, acc2[2][0]); acc2[2][1] = fma2(az, bp.y, acc2[2][1]);
            acc2[3][0] = fma2(aw, bp.x, acc2[3][0]); acc2[3][1] = fma2(aw, bp.y, acc2[3][1]);
        }
        __syncthreads();
    }

    const size_t obase = (size_t)b * outBS;
#pragma unroll
    for (int i = 0; i < 4; i++) {
        int m = m0 + ty * 4 + i;
        float bsv = bu[mrow + ty * 4 + i];
        float p0, p1, p2, p3;
        upk2(acc2[i][0], p0, p1);
        upk2(acc2[i][1], p2, p3);
        float4 r = make_float4(p0 + bsv, p1 + bsv, p2 + bsv, p3 + bsv);
        if (EPI == 1) {
            r.x = r.x / (1.f + __expf(-r.x));
            r.y = r.y / (1.f + __expf(-r.y));
            r.z = r.z / (1.f + __expf(-r.z));
            r.w = r.w / (1.f + __expf(-r.w));
        }
        size_t off = obase + (size_t)m * NTOK + n0 + tx * 4;
        if (EPI == 2) {
            float4 rv = *(const float4*)&res[off];
            r.x += rv.x; r.y += rv.y; r.z += rv.z; r.w += rv.w;
        }
        *(float4*)&out[off] = r;
    }
}

// ================= proj GEMM: X-read = Xa + Xadd (o + pe), residual add ======
__global__ void __launch_bounds__(256)
gemm_add(int Cin,
         const float* __restrict__ W, const float* __restrict__ bias,
         const float* __restrict__ Xa, const float* __restrict__ Xadd, int xBS,
         float* __restrict__ out, int outBS,
         const float* __restrict__ res)
{
    const int b  = blockIdx.z;
    const int n0 = blockIdx.x * 64;
    const int m0 = blockIdx.y * 64;
    const float* Xb = Xa   + (size_t)b * xBS;
    const float* Pb = Xadd + (size_t)b * xBS;

    __shared__ __align__(16) float ws[16][68];
    __shared__ __align__(16) float xs[16][68];

    const int tx = threadIdx.x & 15;
    const int ty = threadIdx.x >> 4;
    const int wr = threadIdx.x >> 2;
    const int wk = (threadIdx.x & 3) << 2;

    unsigned long long acc2[4][2] = {};

    for (int k0 = 0; k0 < Cin; k0 += 16) {
        float4 wv = *(const float4*)&W [(size_t)(m0 + wr) * Cin + k0 + wk];
        size_t xoff = (size_t)(k0 + ty) * NTOK + n0 + tx * 4;
        float4 xv = *(const float4*)&Xb[xoff];
        float4 pv = *(const float4*)&Pb[xoff];
        xv.x += pv.x; xv.y += pv.y; xv.z += pv.z; xv.w += pv.w;
        __syncthreads();
        ws[wk + 0][wr] = wv.x; ws[wk + 1][wr] = wv.y;
        ws[wk + 2][wr] = wv.z; ws[wk + 3][wr] = wv.w;
        *(float4*)&xs[ty][tx * 4] = xv;
        __syncthreads();
#pragma unroll
        for (int k = 0; k < 16; k++) {
            float4 a = *(float4*)&ws[k][ty * 4];
            ulonglong2 bp = *(const ulonglong2*)&xs[k][tx * 4];
            unsigned long long ax = pk2(a.x, a.x), ay = pk2(a.y, a.y);
            unsigned long long az = pk2(a.z, a.z), aw = pk2(a.w, a.w);
            acc2[0][0] = fma2(ax, bp.x, acc2[0][0]); acc2[0][1] = fma2(ax, bp.y, acc2[0][1]);
            acc2[1][0] = fma2(ay, bp.x, acc2[1][0]); acc2[1][1] = fma2(ay, bp.y, acc2[1][1]);
            acc2[2][0] = fma2(az, bp.x, acc2[2][0]); acc2[2][1] = fma2(az, bp.y, acc2[2][1]);
            acc2[3][0] = fma2(aw, bp.x, acc2[3][0]); acc2[3][1] = fma2(aw, bp.y, acc2[3][1]);
        }
    }

    const size_t obase = (size_t)b * outBS;
#pragma unroll
    for (int i = 0; i < 4; i++) {
        int m = m0 + ty * 4 + i;
        float bsv = bias[m];
        float p0, p1, p2, p3;
        upk2(acc2[i][0], p0, p1);
        upk2(acc2[i][1], p2, p3);
        float4 r = make_float4(p0 + bsv, p1 + bsv, p2 + bsv, p3 + bsv);
        size_t off = obase + (size_t)m * NTOK + n0 + tx * 4;
        float4 rv = *(const float4*)&res[off];
        r.x += rv.x; r.y += rv.y; r.z += rv.z; r.w += rv.w;
        *(float4*)&out[off] = r;
    }
}

// ================= fused attention + depthwise conv (one launch) =============
// blocks [0,144): flash attention, 2 queries/thread (n, n+1152)
// blocks [144,656): depthwise 7x7 conv on v_full -> g_pe
__global__ void __launch_bounds__(128, 1)
attn_dw_k(const float* __restrict__ pe_w, const float* __restrict__ pe_b)
{
    __shared__ __align__(16) float smbuf[4096];  // 16KB, role-dependent layout
    const int bid = blockIdx.x;
    const int tid = threadIdx.x;

    if (bid < 144) {
        // ---------------- attention ----------------
        const int bx = bid % 9;
        const int h  = (bid / 9) & 7;
        const int b  = bid / 72;
        const int n0 = bx * 128 + tid;
        const int n1 = n0 + 1152;

        float (*ks)[32][32] = (float(*)[32][32])smbuf;          // [2][32][32]
        float (*vs)[32][32] = (float(*)[32][32])(smbuf + 2048); // [2][32][32]

        const float* base = g_qkv + (size_t)b * 768 * NTOK;
        const float* qb = base + (size_t)(h * 64)       * NTOK;
        const float* kb = base + (size_t)(h * 64 + 32)  * NTOK;
        const float* vb = base + (size_t)(512 + h * 32) * NTOK;
        const float scale = 0.17677669529663687f;  // 1/sqrt(32)

        float q0[32], q1[32];
#pragma unroll
        for (int d = 0; d < 32; d++) {
            q0[d] = qb[(size_t)d * NTOK + n0] * scale;
            q1[d] = qb[(size_t)d * NTOK + n1] * scale;
        }
        float o0[32], o1[32];
#pragma unroll
        for (int d = 0; d < 32; d++) { o0[d] = 0.f; o1[d] = 0.f; }
        float mx0 = -1e30f, mx1 = -1e30f, l0 = 0.f, l1 = 0.f;

        const int f0 = tid * 2;
        {
#pragma unroll
            for (int r = 0; r < 2; r++) {
                int f = f0 + r;
                int d = f >> 3, c = (f & 7) * 4;
                cpasync16(&ks[0][d][c], &kb[(size_t)d * NTOK + c]);
                cpasync16(&vs[0][d][c], &vb[(size_t)d * NTOK + c]);
            }
            cpasync_commit();
        }

        for (int t = 0; t < NTOK / 32; t++) {
            const int cur = t & 1;
            if (t + 1 < NTOK / 32) {
                const int m0 = (t + 1) * 32;
                const int nb = cur ^ 1;
#pragma unroll
                for (int r = 0; r < 2; r++) {
                    int f = f0 + r;
                    int d = f >> 3, c = (f & 7) * 4;
                    cpasync16(&ks[nb][d][c], &kb[(size_t)d * NTOK + m0 + c]);
                    cpasync16(&vs[nb][d][c], &vb[(size_t)d * NTOK + m0 + c]);
                }
                cpasync_commit();
                asm volatile("cp.async.wait_group 1;");
            } else {
                asm volatile("cp.async.wait_group 0;");
            }
            __syncthreads();

            unsigned long long s0[16], s1[16];
#pragma unroll
            for (int j = 0; j < 16; j++) { s0[j] = 0ull; s1[j] = 0ull; }

#pragma unroll 4
            for (int d = 0; d < 32; d++) {
                unsigned long long qd0 = pk2(q0[d], q0[d]);
                unsigned long long qd1 = pk2(q1[d], q1[d]);
                const ulonglong2* kr = (const ulonglong2*)&ks[cur][d][0];
#pragma unroll
                for (int j = 0; j < 8; j++) {
                    ulonglong2 kk = kr[j];
                    s0[2*j]   = fma2(qd0, kk.x, s0[2*j]);
                    s0[2*j+1] = fma2(qd0, kk.y, s0[2*j+1]);
                    s1[2*j]   = fma2(qd1, kk.x, s1[2*j]);
                    s1[2*j+1] = fma2(qd1, kk.y, s1[2*j+1]);
                }
            }

            float tm0 = mx0, tm1 = mx1;
#pragma unroll
            for (int j = 0; j < 16; j++) {
                float a, c;
                upk2(s0[j], a, c); tm0 = fmaxf(tm0, fmaxf(a, c));
                upk2(s1[j], a, c); tm1 = fmaxf(tm1, fmaxf(a, c));
            }
            float corr0 = __expf(mx0 - tm0); mx0 = tm0;
            float corr1 = __expf(mx1 - tm1); mx1 = tm1;
            float ps0 = 0.f, ps1 = 0.f;
#pragma unroll
            for (int j = 0; j < 16; j++) {
                float a, c;
                upk2(s0[j], a, c);
                a = __expf(a - tm0); c = __expf(c - tm0);
                ps0 += a + c; s0[j] = pk2(a, c);
                upk2(s1[j], a, c);
                a = __expf(a - tm1); c = __expf(c - tm1);
                ps1 += a + c; s1[j] = pk2(a, c);
            }
            l0 = l0 * corr0 + ps0;
            l1 = l1 * corr1 + ps1;

#pragma unroll 4
            for (int d = 0; d < 32; d++) {
                const ulonglong2* vr = (const ulonglong2*)&vs[cur][d][0];
                unsigned long long a0 = 0ull, a1 = 0ull;
#pragma unroll
                for (int j = 0; j < 8; j++) {
                    ulonglong2 vv = vr[j];
                    a0 = fma2(s0[2*j], vv.x, a0);
                    a0 = fma2(s0[2*j+1], vv.y, a0);
                    a1 = fma2(s1[2*j], vv.x, a1);
                    a1 = fma2(s1[2*j+1], vv.y, a1);
                }
                float x, y;
                upk2(a0, x, y); o0[d] = o0[d] * corr0 + (x + y);
                upk2(a1, x, y); o1[d] = o1[d] * corr1 + (x + y);
            }
            __syncthreads();
        }

        float inv0 = 1.f / l0, inv1 = 1.f / l1;
        float* ob = g_o + (size_t)b * CCH * NTOK + (size_t)(h * 32) * NTOK;
#pragma unroll
        for (int d = 0; d < 32; d++) {
            ob[(size_t)d * NTOK + n0] = o0[d] * inv0;
            ob[(size_t)d * NTOK + n1] = o1[d] * inv1;
        }
    } else {
        // ---------------- depthwise 7x7 conv -> g_pe ----------------
        const int c2 = bid - 144;
        const int ch = c2 & 255;
        const int b  = c2 >> 8;

        float (*sm)[54] = (float(*)[54])smbuf;          // 54x54 halo
        float* wloc = smbuf + 54 * 54;                  // 49 weights

        const float* src = g_qkv + (size_t)b * 768 * NTOK + (size_t)(512 + ch) * NTOK;
        if (tid < 49) wloc[tid] = pe_w[ch * 49 + tid];

        for (int i = tid; i < 54 * 54; i += 128) {
            int r = i / 54, c = i % 54;
            int rr = r - 3, cc = c - 3;
            float v = 0.f;
            if (rr >= 0 && rr < HS && cc >= 0 && cc < HS) v = src[rr * HS + cc];
            sm[r][c] = v;
        }
        __syncthreads();

        float bs = pe_b[ch];
        float* dst = g_pe + (size_t)b * CCH * NTOK + (size_t)ch * NTOK;
#pragma unroll
        for (int p = 0; p < 18; p++) {
            int pix = tid + p * 128;
            int r = pix / HS, c = pix % HS;
            float acc = bs;
#pragma unroll
            for (int kr = 0; kr < 7; kr++)
#pragma unroll
                for (int kc = 0; kc < 7; kc++)
                    acc += sm[r + kr][c + kc] * wloc[kr * 7 + kc];
            dst[pix] = acc;
        }
    }
}

// ---------------- launch ----------------
extern "C" void kernel_launch(void* const* d_in, const int* in_sizes, int n_in,
                              void* d_out, int out_size)
{
    const float* x      = (const float*)d_in[0];
    const float* qk_w   = (const float*)d_in[1];
    const float* qk_b   = (const float*)d_in[2];
    const float* v_w    = (const float*)d_in[3];
    const float* v_b    = (const float*)d_in[4];
    const float* pe_w   = (const float*)d_in[5];
    const float* pe_b   = (const float*)d_in[6];
    const float* proj_w = (const float*)d_in[7];
    const float* proj_b = (const float*)d_in[8];
    const float* fc1_w  = (const float*)d_in[9];
    const float* fc1_b  = (const float*)d_in[10];
    const float* fc2_w  = (const float*)d_in[11];
    const float* fc2_b  = (const float*)d_in[12];
    float* out = (float*)d_out;

    float *qkv, *o, *pe, *x1, *hb;
    cudaGetSymbolAddress((void**)&qkv, g_qkv);
    cudaGetSymbolAddress((void**)&o,   g_o);
    cudaGetSymbolAddress((void**)&pe,  g_pe);
    cudaGetSymbolAddress((void**)&x1,  g_x1);
    cudaGetSymbolAddress((void**)&hb,  g_h);

    dim3 t256(256);
    const int BIG = 1 << 30;
    // fused qk (rows 0..511) + v (rows 512..767), one cp.async-pipelined launch
    gemm_db<0><<<dim3(36, 12, BB), t256>>>(256, qk_w, qk_b, v_w, v_b, 512,
                                           x, 256 * NTOK,
                                           qkv, 768 * NTOK, nullptr);
    // attention (-> g_o) co-scheduled with depthwise conv (-> g_pe)
    attn_dw_k<<<656, 128>>>(pe_w, pe_b);
    // proj on (o + pe) + residual x -> x1
    gemm_add<<<dim3(36, 4, BB), t256>>>(256, proj_w, proj_b,
                                        o, pe, 256 * NTOK,
                                        x1, 256 * NTOK, x);
    // fc1 + silu -> h
    gemm_db<1><<<dim3(36, 8, BB), t256>>>(256, fc1_w, fc1_b, nullptr, nullptr, BIG,
                                          x1, 256 * NTOK,
                                          hb, 512 * NTOK, nullptr);
    // fc2 + residual x1 -> out
    gemm_db<2><<<dim3(36, 4, BB), t256>>>(512, fc2_w, fc2_b, nullptr, nullptr, BIG,
                                          hb, 512 * NTOK,
                                          out, 256 * NTOK, x1);
}

// round 12
// speedup vs baseline: 1.5319x; 1.5319x over previous
#include <cuda_runtime.h>
#include <cstddef>

#define NTOK 2304   // 48*48
#define CCH  256
#define BB   2
#define HS   48

// ---------------- scratch (no allocations allowed) ----------------
__device__ float g_qkv[(size_t)BB * 768 * NTOK];  // rows 0..511 = qk, 512..767 = v
__device__ float g_o  [(size_t)BB * CCH * NTOK];  // attention out, then += pe
__device__ float g_x1 [(size_t)BB * CCH * NTOK];
__device__ float g_h  [(size_t)BB * 512 * NTOK];

// ---------------- packed f32x2 helpers (SASS FFMA2 — only reachable via PTX) ----
__device__ __forceinline__ unsigned long long pk2(float lo, float hi) {
    unsigned long long r;
    asm("mov.b64 %0, {%1, %2};" : "=l"(r) : "f"(lo), "f"(hi));
    return r;
}
__device__ __forceinline__ void upk2(unsigned long long v, float& lo, float& hi) {
    asm("mov.b64 {%0, %1}, %2;" : "=f"(lo), "=f"(hi) : "l"(v));
}
__device__ __forceinline__ unsigned long long fma2(unsigned long long a,
                                                   unsigned long long b,
                                                   unsigned long long c) {
    unsigned long long d;
    asm("fma.rn.f32x2 %0, %1, %2, %3;" : "=l"(d) : "l"(a), "l"(b), "l"(c));
    return d;
}

// ---------------- cp.async helpers (attention K/V staging) ----------------
__device__ __forceinline__ void cpasync16(const void* smem, const void* gmem) {
    unsigned sa = (unsigned)__cvta_generic_to_shared(smem);
    asm volatile("cp.async.cg.shared.global [%0], [%1], 16;" :: "r"(sa), "l"(gmem));
}
__device__ __forceinline__ void cpasync_commit() {
    asm volatile("cp.async.commit_group;");
}

// ================= register-prefetch pipelined GEMM =========================
// out[b][m][n] = sum_k W[m][k] * X[b][k][n] + bias[m]
// EPI: 0 none, 1 silu, 2 residual-add(res). Blocks with m0>=msplit use W2/b2.
// Global loads for tile t+1 are issued BEFORE computing tile t, so L2/DRAM
// latency hides behind the 16-k FMA2 burst (R8 exposed it every step).
template<int EPI>
__global__ void __launch_bounds__(256)
gemm_k(int Cin,
       const float* __restrict__ W, const float* __restrict__ bias,
       const float* __restrict__ W2, const float* __restrict__ b2, int msplit,
       const float* __restrict__ X, int xBS,
       float* __restrict__ out, int outBS,
       const float* __restrict__ res)
{
    const int b  = blockIdx.z;
    const int n0 = blockIdx.x * 64;
    const int m0 = blockIdx.y * 64;
    const float* Xb = X + (size_t)b * xBS;

    const float* Wu = W;
    const float* bu = bias;
    int mrow = m0;
    if (m0 >= msplit) { Wu = W2; bu = b2; mrow = m0 - msplit; }

    __shared__ __align__(16) float ws[16][68];  // [k][m] transposed, conflict-free
    __shared__ __align__(16) float xs[16][68];  // [k][n]

    const int tx = threadIdx.x & 15;
    const int ty = threadIdx.x >> 4;
    const int wr = threadIdx.x >> 2;        // 0..63
    const int wk = (threadIdx.x & 3) << 2;  // 0,4,8,12

    unsigned long long acc2[4][2] = {};

    const float* wp = &Wu[(size_t)(mrow + wr) * Cin + wk];
    const float* xp = &Xb[(size_t)ty * NTOK + n0 + tx * 4];

    // prefetch tile 0 into registers
    float4 wv = *(const float4*)wp;
    float4 xv = *(const float4*)xp;

    const int steps = Cin >> 4;
    for (int t = 0; t < steps; t++) {
        __syncthreads();
        ws[wk + 0][wr] = wv.x; ws[wk + 1][wr] = wv.y;
        ws[wk + 2][wr] = wv.z; ws[wk + 3][wr] = wv.w;
        *(float4*)&xs[ty][tx * 4] = xv;
        __syncthreads();

        if (t + 1 < steps) {                 // issue next tile's LDGs NOW,
            wp += 16;                        // consumed only at next store —
            xp += (size_t)16 * NTOK;         // latency hidden by compute below
            wv = *(const float4*)wp;
            xv = *(const float4*)xp;
        }

#pragma unroll
        for (int k = 0; k < 16; k++) {
            float4 a = *(float4*)&ws[k][ty * 4];
            ulonglong2 bp = *(const ulonglong2*)&xs[k][tx * 4];
            unsigned long long ax = pk2(a.x, a.x), ay = pk2(a.y, a.y);
            unsigned long long az = pk2(a.z, a.z), aw = pk2(a.w, a.w);
            acc2[0][0] = fma2(ax, bp.x, acc2[0][0]); acc2[0][1] = fma2(ax, bp.y, acc2[0][1]);
            acc2[1][0] = fma2(ay, bp.x, acc2[1][0]); acc2[1][1] = fma2(ay, bp.y, acc2[1][1]);
            acc2[2][0] = fma2(az, bp.x, acc2[2][0]); acc2[2][1] = fma2(az, bp.y, acc2[2][1]);
            acc2[3][0] = fma2(aw, bp.x, acc2[3][0]); acc2[3][1] = fma2(aw, bp.y, acc2[3][1]);
        }
    }

    const size_t obase = (size_t)b * outBS;
#pragma unroll
    for (int i = 0; i < 4; i++) {
        int m = m0 + ty * 4 + i;
        float bsv = bu[mrow + ty * 4 + i];
        float p0, p1, p2, p3;
        upk2(acc2[i][0], p0, p1);
        upk2(acc2[i][1], p2, p3);
        float4 r = make_float4(p0 + bsv, p1 + bsv, p2 + bsv, p3 + bsv);
        if (EPI == 1) {
            r.x = r.x / (1.f + __expf(-r.x));
            r.y = r.y / (1.f + __expf(-r.y));
            r.z = r.z / (1.f + __expf(-r.z));
            r.w = r.w / (1.f + __expf(-r.w));
        }
        size_t off = obase + (size_t)m * NTOK + n0 + tx * 4;
        if (EPI == 2) {
            float4 rv = *(const float4*)&res[off];
            r.x += rv.x; r.y += rv.y; r.z += rv.z; r.w += rv.w;
        }
        *(float4*)&out[off] = r;
    }
}

// ---------------- flash attention: each thread owns TWO queries (n, n+1152) ----
// Shared K/V loads amortized over both queries: 1 LDS.128 -> 4 FMA2.
// 32-key tiles, 2-stage cp.async pipeline for K/V staging.  (R8-proven form.)
__global__ void __launch_bounds__(128, 1)
attn_k()
{
    const int b = blockIdx.z, h = blockIdx.y;
    const int n0 = blockIdx.x * 128 + threadIdx.x;
    const int n1 = n0 + 1152;

    const float* base = g_qkv + (size_t)b * 768 * NTOK;
    const float* qb = base + (size_t)(h * 64)       * NTOK;
    const float* kb = base + (size_t)(h * 64 + 32)  * NTOK;
    const float* vb = base + (size_t)(512 + h * 32) * NTOK;
    const float scale = 0.17677669529663687f;  // 1/sqrt(32)

    float q0[32], q1[32];
#pragma unroll
    for (int d = 0; d < 32; d++) {
        q0[d] = qb[(size_t)d * NTOK + n0] * scale;
        q1[d] = qb[(size_t)d * NTOK + n1] * scale;
    }

    float o0[32], o1[32];
#pragma unroll
    for (int d = 0; d < 32; d++) { o0[d] = 0.f; o1[d] = 0.f; }
    float mx0 = -1e30f, mx1 = -1e30f, l0 = 0.f, l1 = 0.f;

    __shared__ __align__(16) float ks[2][32][32];
    __shared__ __align__(16) float vs[2][32][32];

    const int f0 = threadIdx.x * 2;  // each thread stages 2 float4 per array

    {
#pragma unroll
        for (int r = 0; r < 2; r++) {
            int f = f0 + r;              // 0..255
            int d = f >> 3, c = (f & 7) * 4;
            cpasync16(&ks[0][d][c], &kb[(size_t)d * NTOK + c]);
            cpasync16(&vs[0][d][c], &vb[(size_t)d * NTOK + c]);
        }
        cpasync_commit();
    }

    for (int t = 0; t < NTOK / 32; t++) {
        const int cur = t & 1;
        if (t + 1 < NTOK / 32) {
            const int m0 = (t + 1) * 32;
            const int nb = cur ^ 1;
#pragma unroll
            for (int r = 0; r < 2; r++) {
                int f = f0 + r;
                int d = f >> 3, c = (f & 7) * 4;
                cpasync16(&ks[nb][d][c], &kb[(size_t)d * NTOK + m0 + c]);
                cpasync16(&vs[nb][d][c], &vb[(size_t)d * NTOK + m0 + c]);
            }
            cpasync_commit();
            asm volatile("cp.async.wait_group 1;");
        } else {
            asm volatile("cp.async.wait_group 0;");
        }
        __syncthreads();

        // ---- QK^T: 32 scores per query, packed as 16 key-pairs ----
        unsigned long long s0[16], s1[16];
#pragma unroll
        for (int j = 0; j < 16; j++) { s0[j] = 0ull; s1[j] = 0ull; }

#pragma unroll 4
        for (int d = 0; d < 32; d++) {
            unsigned long long qd0 = pk2(q0[d], q0[d]);
            unsigned long long qd1 = pk2(q1[d], q1[d]);
            const ulonglong2* kr = (const ulonglong2*)&ks[cur][d][0];
#pragma unroll
            for (int j = 0; j < 8; j++) {
                ulonglong2 kk = kr[j];
                s0[2*j]   = fma2(qd0, kk.x, s0[2*j]);
                s0[2*j+1] = fma2(qd0, kk.y, s0[2*j+1]);
                s1[2*j]   = fma2(qd1, kk.x, s1[2*j]);
                s1[2*j+1] = fma2(qd1, kk.y, s1[2*j+1]);
            }
        }

        // ---- online softmax (thread-local) ----
        float tm0 = mx0, tm1 = mx1;
#pragma unroll
        for (int j = 0; j < 16; j++) {
            float a, c;
            upk2(s0[j], a, c); tm0 = fmaxf(tm0, fmaxf(a, c));
            upk2(s1[j], a, c); tm1 = fmaxf(tm1, fmaxf(a, c));
        }
        float corr0 = __expf(mx0 - tm0); mx0 = tm0;
        float corr1 = __expf(mx1 - tm1); mx1 = tm1;
        float ps0 = 0.f, ps1 = 0.f;
#pragma unroll
        for (int j = 0; j < 16; j++) {
            float a, c;
            upk2(s0[j], a, c);
            a = __expf(a - tm0); c = __expf(c - tm0);
            ps0 += a + c; s0[j] = pk2(a, c);
            upk2(s1[j], a, c);
            a = __expf(a - tm1); c = __expf(c - tm1);
            ps1 += a + c; s1[j] = pk2(a, c);
        }
        l0 = l0 * corr0 + ps0;
        l1 = l1 * corr1 + ps1;

        // ---- P·V ----
#pragma unroll 4
        for (int d = 0; d < 32; d++) {
            const ulonglong2* vr = (const ulonglong2*)&vs[cur][d][0];
            unsigned long long a0 = 0ull, a1 = 0ull;
#pragma unroll
            for (int j = 0; j < 8; j++) {
                ulonglong2 vv = vr[j];
                a0 = fma2(s0[2*j], vv.x, a0);
                a0 = fma2(s0[2*j+1], vv.y, a0);
                a1 = fma2(s1[2*j], vv.x, a1);
                a1 = fma2(s1[2*j+1], vv.y, a1);
            }
            float x, y;
            upk2(a0, x, y); o0[d] = o0[d] * corr0 + (x + y);
            upk2(a1, x, y); o1[d] = o1[d] * corr1 + (x + y);
        }
        __syncthreads();
    }

    float inv0 = 1.f / l0, inv1 = 1.f / l1;
    float* ob = g_o + (size_t)b * CCH * NTOK + (size_t)(h * 32) * NTOK;
#pragma unroll
    for (int d = 0; d < 32; d++) {
        ob[(size_t)d * NTOK + n0] = o0[d] * inv0;
        ob[(size_t)d * NTOK + n1] = o1[d] * inv1;
    }
}

// ---------------- depthwise 7x7 SAME conv on v_full; adds (pe + pe_b) into g_o ----
__global__ void __launch_bounds__(256)
dwconv_k(const float* __restrict__ pe_w, const float* __restrict__ pe_b)
{
    const int ch = blockIdx.x;
    const int b  = blockIdx.y;
    __shared__ float sm[54][54];
    __shared__ float wloc[49];

    const float* src = g_qkv + (size_t)b * 768 * NTOK + (size_t)(512 + ch) * NTOK;
    const int tid = threadIdx.x;
    if (tid < 49) wloc[tid] = pe_w[ch * 49 + tid];

    for (int i = tid; i < 54 * 54; i += 256) {
        int r = i / 54, c = i % 54;
        int rr = r - 3, cc = c - 3;
        float v = 0.f;
        if (rr >= 0 && rr < HS && cc >= 0 && cc < HS) v = src[rr * HS + cc];
        sm[r][c] = v;
    }
    __syncthreads();

    float bs = pe_b[ch];
    float* dst = g_o + (size_t)b * CCH * NTOK + (size_t)ch * NTOK;
#pragma unroll
    for (int p = 0; p < 9; p++) {
        int pix = tid + p * 256;
        int r = pix / HS, c = pix % HS;
        float acc = bs;
#pragma unroll
        for (int kr = 0; kr < 7; kr++)
#pragma unroll
            for (int kc = 0; kc < 7; kc++)
                acc += sm[r + kr][c + kc] * wloc[kr * 7 + kc];
        dst[pix] += acc;
    }
}

// ---------------- launch ----------------
extern "C" void kernel_launch(void* const* d_in, const int* in_sizes, int n_in,
                              void* d_out, int out_size)
{
    const float* x      = (const float*)d_in[0];
    const float* qk_w   = (const float*)d_in[1];
    const float* qk_b   = (const float*)d_in[2];
    const float* v_w    = (const float*)d_in[3];
    const float* v_b    = (const float*)d_in[4];
    const float* pe_w   = (const float*)d_in[5];
    const float* pe_b   = (const float*)d_in[6];
    const float* proj_w = (const float*)d_in[7];
    const float* proj_b = (const float*)d_in[8];
    const float* fc1_w  = (const float*)d_in[9];
    const float* fc1_b  = (const float*)d_in[10];
    const float* fc2_w  = (const float*)d_in[11];
    const float* fc2_b  = (const float*)d_in[12];
    float* out = (float*)d_out;

    float *qkv, *o, *x1, *hb;
    cudaGetSymbolAddress((void**)&qkv, g_qkv);
    cudaGetSymbolAddress((void**)&o,   g_o);
    cudaGetSymbolAddress((void**)&x1,  g_x1);
    cudaGetSymbolAddress((void**)&hb,  g_h);

    dim3 t256(256);
    const int BIG = 1 << 30;
    // fused qk (rows 0..511) + v (rows 512..767) in ONE launch
    gemm_k<0><<<dim3(36, 12, BB), t256>>>(256, qk_w, qk_b, v_w, v_b, 512,
                                          x, 256 * NTOK,
                                          qkv, 768 * NTOK, nullptr);
    // attention -> g_o   (2 queries per thread)
    attn_k<<<dim3(9, 8, BB), 128>>>();
    // pe (depthwise 7x7 on v_full) += into g_o
    dwconv_k<<<dim3(CCH, BB), t256>>>(pe_w, pe_b);
    // proj + residual x -> x1
    gemm_k<2><<<dim3(36, 4, BB), t256>>>(256, proj_w, proj_b, nullptr, nullptr, BIG,
                                         o, 256 * NTOK,
                                         x1, 256 * NTOK, x);
    // fc1 + silu -> h
    gemm_k<1><<<dim3(36, 8, BB), t256>>>(256, fc1_w, fc1_b, nullptr, nullptr, BIG,
                                         x1, 256 * NTOK,
                                         hb, 512 * NTOK, nullptr);
    // fc2 + residual x1 -> out
    gemm_k<2><<<dim3(36, 4, BB), t256>>>(512, fc2_w, fc2_b, nullptr, nullptr, BIG,
                                         hb, 512 * NTOK,
                                         out, 256 * NTOK, x1);
}